// round 5
// baseline (speedup 1.0000x reference)
#include <cuda_runtime.h>

// Problem constants (match reference)
#define N_DATA    500000
#define FEAT_DIM  512
#define NUM_CLASS 10000
#define BATCH     8192
#define MOMENTUM  0.9f

#define LAT_ELEMS   ((long long)N_DATA * FEAT_DIM)      // 256,000,000
#define CS_ELEMS    ((long long)NUM_CLASS * FEAT_DIM)   //   5,120,000

#define ROW_F4      (FEAT_DIM / 4)          // 128 float4 per row
#define COPY_BLOCKS 4096
#define N_CS4       ((int)(CS_ELEMS / 4))   // 1,280,000 float4
#define MASK_INT4   (N_DATA / 16)           // 31250 int4 covering the byte mask

// Per-row "this row will be rewritten by the update" flag.
__device__ unsigned char g_mask[N_DATA];

// ---------------------------------------------------------------------------
// Kernel 1: zero out_cs (output is poisoned 0xAA) and clear the row mask.
// ~20.5 MB of writes, full-grid, ~3 us.
// ---------------------------------------------------------------------------
__global__ void zero_kernel(float4* __restrict__ out_cs)
{
    const int total = N_CS4 + MASK_INT4;
    int stride = gridDim.x * blockDim.x;
    float4 zf = make_float4(0.f, 0.f, 0.f, 0.f);
    int4   zi = make_int4(0, 0, 0, 0);
    for (int i = blockIdx.x * blockDim.x + threadIdx.x; i < total; i += stride) {
        if (i < N_CS4) out_cs[i] = zf;
        else           ((int4*)g_mask)[i - N_CS4] = zi;
    }
}

// ---------------------------------------------------------------------------
// Kernel 2: mark the 8192 rows the update will rewrite.
// ---------------------------------------------------------------------------
__global__ void set_mask_kernel(const int* __restrict__ idx)
{
    int i = blockIdx.x * blockDim.x + threadIdx.x;
    if (i < BATCH) g_mask[idx[i]] = 1;
}

// ---------------------------------------------------------------------------
// Kernel 3 (mega, fused). NO inter-block synchronization anywhere:
//   - out_cs starts at zero; the cs base copy (copy blocks) and the batch
//     contributions (update blocks) BOTH use atomicAdd, so any interleaving
//     yields the correct sum.
//   blocks [0, COPY_BLOCKS): atomicAdd cs base into out_cs, then stream-copy
//     all non-masked lat rows.
//   blocks [COPY_BLOCKS, COPY_BLOCKS+BATCH): blend + normalize + scatter row,
//     atomicAdd class contribution.
// ---------------------------------------------------------------------------
__global__ __launch_bounds__(128)
void fused_kernel(const float*  __restrict__ batch,
                  const float*  __restrict__ lat,
                  const float*  __restrict__ cs,
                  const int*    __restrict__ targets,
                  const int*    __restrict__ idx,
                  float* __restrict__ out_lat,
                  float* __restrict__ out_cs)
{
    const int t = threadIdx.x;   // 0..127

    if (blockIdx.x < COPY_BLOCKS) {
        const int cb = blockIdx.x;

        // ---- class_sums base: add into zeroed out_cs (order-free) ----
        {
            const float4* src = (const float4*)cs;
            for (int i = cb * 128 + t; i < N_CS4; i += COPY_BLOCKS * 128) {
                float4 v = src[i];
                float* d = (float*)(out_cs) + (long long)i * 4;
                atomicAdd(d + 0, v.x);
                atomicAdd(d + 1, v.y);
                atomicAdd(d + 2, v.z);
                atomicAdd(d + 3, v.w);
            }
        }

        // ---- masked streaming copy of lat rows (2-row unroll for MLP) ----
        const float4* src = (const float4*)lat;
        float4*       dst = (float4*)out_lat;

        for (int r = cb; r < N_DATA; r += 2 * COPY_BLOCKS) {
            int r2 = r + COPY_BLOCKS;
            unsigned char m1 = g_mask[r];
            float4 v1 = __ldcs(src + r * ROW_F4 + t);
            unsigned char m2 = 0;
            float4 v2;
            if (r2 < N_DATA) {
                m2 = g_mask[r2];
                v2 = __ldcs(src + r2 * ROW_F4 + t);
            }
            if (!m1) __stcs(dst + r * ROW_F4 + t, v1);
            if (r2 < N_DATA && !m2) __stcs(dst + r2 * ROW_F4 + t, v2);
        }
    } else {
        // ---------------- update path ----------------
        const int row     = blockIdx.x - COPY_BLOCKS;
        const int src_row = idx[row];
        const int cls     = targets[row];

        const float4* lat_row   = (const float4*)(lat)   + src_row * ROW_F4;
        const float4* batch_row = (const float4*)(batch) + row     * ROW_F4;

        float4 a = lat_row[t];
        float4 b = batch_row[t];

        float4 v;
        v.x = a.x * (1.0f - MOMENTUM) + b.x * MOMENTUM;
        v.y = a.y * (1.0f - MOMENTUM) + b.y * MOMENTUM;
        v.z = a.z * (1.0f - MOMENTUM) + b.z * MOMENTUM;
        v.w = a.w * (1.0f - MOMENTUM) + b.w * MOMENTUM;

        float ss = v.x * v.x + v.y * v.y + v.z * v.z + v.w * v.w;

        #pragma unroll
        for (int off = 16; off > 0; off >>= 1)
            ss += __shfl_xor_sync(0xFFFFFFFFu, ss, off);

        __shared__ float warp_sums[4];
        const int lane = t & 31, wid = t >> 5;
        if (lane == 0) warp_sums[wid] = ss;
        __syncthreads();
        float total = warp_sums[0] + warp_sums[1] + warp_sums[2] + warp_sums[3];

        float inv_norm = rsqrtf(total);
        inv_norm = inv_norm * (1.5f - 0.5f * total * inv_norm * inv_norm);

        float4 u;
        u.x = v.x * inv_norm;
        u.y = v.y * inv_norm;
        u.z = v.z * inv_norm;
        u.w = v.w * inv_norm;

        ((float4*)out_lat)[src_row * ROW_F4 + t] = u;

        float* cs_row = out_cs + (long long)cls * FEAT_DIM + t * 4;
        atomicAdd(cs_row + 0, u.x);
        atomicAdd(cs_row + 1, u.y);
        atomicAdd(cs_row + 2, u.z);
        atomicAdd(cs_row + 3, u.w);
    }
}

// ---------------------------------------------------------------------------
// Launch
// ---------------------------------------------------------------------------
extern "C" void kernel_launch(void* const* d_in, const int* in_sizes, int n_in,
                              void* d_out, int out_size)
{
    // metadata order: batch_samples, lat_memory, class_sums, targets, idx
    const float* batch = (const float*)d_in[0];
    const float* lat   = (const float*)d_in[1];
    const float* cs    = (const float*)d_in[2];
    const int*   targ  = (const int*)  d_in[3];
    const int*   idx   = (const int*)  d_in[4];

    float* out_lat = (float*)d_out;
    float* out_cs  = out_lat + LAT_ELEMS;

    // 1: zero out_cs + clear mask (~20.5 MB, ~3 us)
    zero_kernel<<<512, 256>>>((float4*)out_cs);

    // 2: mark updated rows
    set_mask_kernel<<<(BATCH + 255) / 256, 256>>>(idx);

    // 3: fused cs-base-add + update + masked streaming copy (no sync needed)
    fused_kernel<<<COPY_BLOCKS + BATCH, 128>>>(batch, lat, cs, targ, idx,
                                               out_lat, out_cs);
}

// round 8
// speedup vs baseline: 1.0058x; 1.0058x over previous
#include <cuda_runtime.h>

// Problem constants (match reference)
#define N_DATA    500000
#define FEAT_DIM  512
#define NUM_CLASS 10000
#define BATCH     8192
#define MOMENTUM  0.9f

#define LAT_ELEMS   ((long long)N_DATA * FEAT_DIM)      // 256,000,000
#define CS_ELEMS    ((long long)NUM_CLASS * FEAT_DIM)   //   5,120,000

#define ROW_F4      (FEAT_DIM / 4)          // 128 float4 per row
#define COPY_BLOCKS 4096
#define N_CS4       ((int)(CS_ELEMS / 4))   // 1,280,000 float4
#define MASK_INT4   (N_DATA / 16)           // 31250 int4 over the byte mask

// Per-row "this row will be rewritten by the update" flag.
__device__ unsigned char g_mask[N_DATA];

// ---------------------------------------------------------------------------
// Prologue (single launch):
//   block 0           : clear mask (0.5 MB) -> __syncthreads -> set idx flags.
//   blocks 1..grid-1  : stream-copy class_sums base (40 MB) into out_cs.
// The mask work (~2.5 us on one SM) hides entirely under the cs copy (~7 us).
// No block reads the mask or out_cs inside this kernel -> no ordering needed.
// All loops are bounded; no cross-block communication of any kind.
// ---------------------------------------------------------------------------
__global__ __launch_bounds__(256)
void prep_kernel(const float4* __restrict__ cs,
                 float4* __restrict__ out_cs,
                 const int* __restrict__ idx)
{
    const int t = threadIdx.x;
    if (blockIdx.x == 0) {
        const int4 z = make_int4(0, 0, 0, 0);
        for (int i = t; i < MASK_INT4; i += 256)
            ((int4*)g_mask)[i] = z;
        __syncthreads();
        for (int i = t; i < BATCH; i += 256)
            g_mask[idx[i]] = 1;
    } else {
        const int nb = gridDim.x - 1;
        for (int i = (blockIdx.x - 1) * 256 + t; i < N_CS4; i += nb * 256)
            __stcs(out_cs + i, __ldcs(cs + i));
    }
}

// ---------------------------------------------------------------------------
// Fused kernel:
//   blocks [0, COPY_BLOCKS): stream-copy all non-masked lat rows. Masks are
//     prefetched one iteration ahead so row loads are conditional (skips the
//     16.8 MB of reads for rows the update rewrites) without putting the mask
//     load latency on the row-load critical path.
//   blocks [COPY_BLOCKS, COPY_BLOCKS+BATCH): blend + normalize + scatter row,
//     atomicAdd class contribution (base already present from prologue).
// ---------------------------------------------------------------------------
__global__ __launch_bounds__(128)
void fused_kernel(const float*  __restrict__ batch,
                  const float*  __restrict__ lat,
                  const int*    __restrict__ targets,
                  const int*    __restrict__ idx,
                  float* __restrict__ out_lat,
                  float* __restrict__ out_cs)
{
    const int t = threadIdx.x;   // 0..127

    if (blockIdx.x < COPY_BLOCKS) {
        const int cb = blockIdx.x;
        const float4* src = (const float4*)lat;
        float4*       dst = (float4*)out_lat;

        int r = cb;
        // prefetch masks for first pair
        unsigned char m1 = g_mask[r];
        unsigned char m2 = (r + COPY_BLOCKS < N_DATA) ? g_mask[r + COPY_BLOCKS] : 1;

        while (r < N_DATA) {
            const int r2 = r + COPY_BLOCKS;
            const int rn = r + 2 * COPY_BLOCKS;

            // prefetch next pair's masks (latency hidden under this pair's copy)
            unsigned char n1 = (rn < N_DATA) ? g_mask[rn] : 1;
            unsigned char n2 = (rn + COPY_BLOCKS < N_DATA) ? g_mask[rn + COPY_BLOCKS] : 1;

            const bool d1 = (m1 == 0);
            const bool d2 = (r2 < N_DATA) && (m2 == 0);

            float4 v1, v2;
            if (d1) v1 = __ldcs(src + (long long)r  * ROW_F4 + t);
            if (d2) v2 = __ldcs(src + (long long)r2 * ROW_F4 + t);
            if (d1) __stcs(dst + (long long)r  * ROW_F4 + t, v1);
            if (d2) __stcs(dst + (long long)r2 * ROW_F4 + t, v2);

            m1 = n1;
            m2 = n2;
            r  = rn;
        }
    } else {
        // ---------------- update path ----------------
        const int row     = blockIdx.x - COPY_BLOCKS;
        const int src_row = idx[row];
        const int cls     = targets[row];

        const float4* lat_row   = (const float4*)(lat)   + (long long)src_row * ROW_F4;
        const float4* batch_row = (const float4*)(batch) + (long long)row     * ROW_F4;

        float4 a = lat_row[t];
        float4 b = batch_row[t];

        float4 v;
        v.x = a.x * (1.0f - MOMENTUM) + b.x * MOMENTUM;
        v.y = a.y * (1.0f - MOMENTUM) + b.y * MOMENTUM;
        v.z = a.z * (1.0f - MOMENTUM) + b.z * MOMENTUM;
        v.w = a.w * (1.0f - MOMENTUM) + b.w * MOMENTUM;

        float ss = v.x * v.x + v.y * v.y + v.z * v.z + v.w * v.w;

        #pragma unroll
        for (int off = 16; off > 0; off >>= 1)
            ss += __shfl_xor_sync(0xFFFFFFFFu, ss, off);

        __shared__ float warp_sums[4];
        const int lane = t & 31, wid = t >> 5;
        if (lane == 0) warp_sums[wid] = ss;
        __syncthreads();
        float total = warp_sums[0] + warp_sums[1] + warp_sums[2] + warp_sums[3];

        float inv_norm = rsqrtf(total);
        inv_norm = inv_norm * (1.5f - 0.5f * total * inv_norm * inv_norm);

        float4 u;
        u.x = v.x * inv_norm;
        u.y = v.y * inv_norm;
        u.z = v.z * inv_norm;
        u.w = v.w * inv_norm;

        ((float4*)out_lat)[(long long)src_row * ROW_F4 + t] = u;

        float* cs_row = out_cs + (long long)cls * FEAT_DIM + t * 4;
        atomicAdd(cs_row + 0, u.x);
        atomicAdd(cs_row + 1, u.y);
        atomicAdd(cs_row + 2, u.z);
        atomicAdd(cs_row + 3, u.w);
    }
}

// ---------------------------------------------------------------------------
// Launch
// ---------------------------------------------------------------------------
extern "C" void kernel_launch(void* const* d_in, const int* in_sizes, int n_in,
                              void* d_out, int out_size)
{
    // metadata order: batch_samples, lat_memory, class_sums, targets, idx
    const float* batch = (const float*)d_in[0];
    const float* lat   = (const float*)d_in[1];
    const float* cs    = (const float*)d_in[2];
    const int*   targ  = (const int*)  d_in[3];
    const int*   idx   = (const int*)  d_in[4];

    float* out_lat = (float*)d_out;
    float* out_cs  = out_lat + LAT_ELEMS;

    // 1: prologue — mask clear+set (block 0) || cs base copy (other blocks)
    prep_kernel<<<2048, 256>>>((const float4*)cs, (float4*)out_cs, idx);

    // 2: fused update + masked streaming copy
    fused_kernel<<<COPY_BLOCKS + BATCH, 128>>>(batch, lat, targ, idx,
                                               out_lat, out_cs);
}

// round 11
// speedup vs baseline: 1.0203x; 1.0144x over previous
#include <cuda_runtime.h>

// Problem constants (match reference)
#define N_DATA    500000
#define FEAT_DIM  512
#define NUM_CLASS 10000
#define BATCH     8192
#define MOMENTUM  0.9f

#define LAT_ELEMS   ((long long)N_DATA * FEAT_DIM)      // 256,000,000
#define CS_ELEMS    ((long long)NUM_CLASS * FEAT_DIM)   //   5,120,000

#define ROW_F4      (FEAT_DIM / 4)          // 128 float4 per row
#define COPY_BLOCKS 4096
#define N_CS4       ((int)(CS_ELEMS / 4))   // 1,280,000 float4
#define MASK_INT4   (N_DATA / 16)           // 31250 int4 over the byte mask

// Per-row "this row will be rewritten by the update" flag.
__device__ unsigned char g_mask[N_DATA];

// ---------------------------------------------------------------------------
// Prologue 1 (fully parallel): clear mask (0.5 MB) AND stream-copy the
// class_sums base (40 MB) into out_cs. Every block grid-strides the combined
// index range — no single-block bottleneck.
// ---------------------------------------------------------------------------
__global__ __launch_bounds__(256)
void prep_kernel(const float4* __restrict__ cs,
                 float4* __restrict__ out_cs)
{
    const int total  = N_CS4 + MASK_INT4;
    const int stride = gridDim.x * blockDim.x;
    const int4 z = make_int4(0, 0, 0, 0);
    for (int i = blockIdx.x * blockDim.x + threadIdx.x; i < total; i += stride) {
        if (i < N_CS4) __stcs(out_cs + i, __ldcs(cs + i));
        else           ((int4*)g_mask)[i - N_CS4] = z;
    }
}

// ---------------------------------------------------------------------------
// Prologue 2 (fully parallel): mark the 8192 rows the update will rewrite.
// Ordering vs the mask clear is provided by the kernel boundary.
// ---------------------------------------------------------------------------
__global__ void set_mask_kernel(const int* __restrict__ idx)
{
    int i = blockIdx.x * blockDim.x + threadIdx.x;
    if (i < BATCH) g_mask[idx[i]] = 1;
}

// ---------------------------------------------------------------------------
// Fused kernel (identical to the R8 version ncu measured at 303.4 us,
// 6.70 TB/s, 84.6% DRAM):
//   blocks [0, COPY_BLOCKS): stream-copy all non-masked lat rows, masks
//     prefetched one iteration ahead so skipped rows cost no read traffic and
//     the mask load latency stays off the row-copy critical path.
//   blocks [COPY_BLOCKS, COPY_BLOCKS+BATCH): blend + normalize + scatter row,
//     atomicAdd class contribution (base already present from prologue).
// ---------------------------------------------------------------------------
__global__ __launch_bounds__(128)
void fused_kernel(const float*  __restrict__ batch,
                  const float*  __restrict__ lat,
                  const int*    __restrict__ targets,
                  const int*    __restrict__ idx,
                  float* __restrict__ out_lat,
                  float* __restrict__ out_cs)
{
    const int t = threadIdx.x;   // 0..127

    if (blockIdx.x < COPY_BLOCKS) {
        const int cb = blockIdx.x;
        const float4* src = (const float4*)lat;
        float4*       dst = (float4*)out_lat;

        int r = cb;
        unsigned char m1 = g_mask[r];
        unsigned char m2 = (r + COPY_BLOCKS < N_DATA) ? g_mask[r + COPY_BLOCKS] : 1;

        while (r < N_DATA) {
            const int r2 = r + COPY_BLOCKS;
            const int rn = r + 2 * COPY_BLOCKS;

            unsigned char n1 = (rn < N_DATA) ? g_mask[rn] : 1;
            unsigned char n2 = (rn + COPY_BLOCKS < N_DATA) ? g_mask[rn + COPY_BLOCKS] : 1;

            const bool d1 = (m1 == 0);
            const bool d2 = (r2 < N_DATA) && (m2 == 0);

            float4 v1, v2;
            if (d1) v1 = __ldcs(src + (long long)r  * ROW_F4 + t);
            if (d2) v2 = __ldcs(src + (long long)r2 * ROW_F4 + t);
            if (d1) __stcs(dst + (long long)r  * ROW_F4 + t, v1);
            if (d2) __stcs(dst + (long long)r2 * ROW_F4 + t, v2);

            m1 = n1;
            m2 = n2;
            r  = rn;
        }
    } else {
        // ---------------- update path ----------------
        const int row     = blockIdx.x - COPY_BLOCKS;
        const int src_row = idx[row];
        const int cls     = targets[row];

        const float4* lat_row   = (const float4*)(lat)   + (long long)src_row * ROW_F4;
        const float4* batch_row = (const float4*)(batch) + (long long)row     * ROW_F4;

        float4 a = lat_row[t];
        float4 b = batch_row[t];

        float4 v;
        v.x = a.x * (1.0f - MOMENTUM) + b.x * MOMENTUM;
        v.y = a.y * (1.0f - MOMENTUM) + b.y * MOMENTUM;
        v.z = a.z * (1.0f - MOMENTUM) + b.z * MOMENTUM;
        v.w = a.w * (1.0f - MOMENTUM) + b.w * MOMENTUM;

        float ss = v.x * v.x + v.y * v.y + v.z * v.z + v.w * v.w;

        #pragma unroll
        for (int off = 16; off > 0; off >>= 1)
            ss += __shfl_xor_sync(0xFFFFFFFFu, ss, off);

        __shared__ float warp_sums[4];
        const int lane = t & 31, wid = t >> 5;
        if (lane == 0) warp_sums[wid] = ss;
        __syncthreads();
        float total = warp_sums[0] + warp_sums[1] + warp_sums[2] + warp_sums[3];

        float inv_norm = rsqrtf(total);
        inv_norm = inv_norm * (1.5f - 0.5f * total * inv_norm * inv_norm);

        float4 u;
        u.x = v.x * inv_norm;
        u.y = v.y * inv_norm;
        u.z = v.z * inv_norm;
        u.w = v.w * inv_norm;

        ((float4*)out_lat)[(long long)src_row * ROW_F4 + t] = u;

        float* cs_row = out_cs + (long long)cls * FEAT_DIM + t * 4;
        atomicAdd(cs_row + 0, u.x);
        atomicAdd(cs_row + 1, u.y);
        atomicAdd(cs_row + 2, u.z);
        atomicAdd(cs_row + 3, u.w);
    }
}

// ---------------------------------------------------------------------------
// Launch
// ---------------------------------------------------------------------------
extern "C" void kernel_launch(void* const* d_in, const int* in_sizes, int n_in,
                              void* d_out, int out_size)
{
    // metadata order: batch_samples, lat_memory, class_sums, targets, idx
    const float* batch = (const float*)d_in[0];
    const float* lat   = (const float*)d_in[1];
    const float* cs    = (const float*)d_in[2];
    const int*   targ  = (const int*)  d_in[3];
    const int*   idx   = (const int*)  d_in[4];

    float* out_lat = (float*)d_out;
    float* out_cs  = out_lat + LAT_ELEMS;

    // 1: mask clear + cs base copy (fully parallel, ~6-7 us)
    prep_kernel<<<2048, 256>>>((const float4*)cs, (float4*)out_cs);

    // 2: mark updated rows (parallel, ~1.5 us)
    set_mask_kernel<<<(BATCH + 255) / 256, 256>>>(idx);

    // 3: fused update + masked streaming copy (measured 303.4 us in R8)
    fused_kernel<<<COPY_BLOCKS + BATCH, 128>>>(batch, lat, targ, idx,
                                               out_lat, out_cs);
}